// round 1
// baseline (speedup 1.0000x reference)
#include <cuda_runtime.h>

#define N_NODES 100000
#define FEAT 16

// Scratch in __device__ globals (no allocations allowed).
__device__ float  g_deg [N_NODES];
__device__ float  g_dinv[N_NODES];
__device__ float4 g_hs1 [N_NODES * 4];   // layer1 transformed+src-scaled features
__device__ float4 g_agg1[N_NODES * 4];   // layer1 aggregation (init = hs1 -> self loop)
__device__ float4 g_hs2 [N_NODES * 4];
__device__ float4 g_agg2[N_NODES * 4];

__device__ __forceinline__ void red_add_v4(float4* p, float4 v) {
    asm volatile("red.global.add.v4.f32 [%0], {%1, %2, %3, %4};"
                 :: "l"(p), "f"(v.x), "f"(v.y), "f"(v.z), "f"(v.w)
                 : "memory");
}

// ---------------------------------------------------------------- degree ----
__global__ void k_deg_init(int n) {
    int i = blockIdx.x * blockDim.x + threadIdx.x;
    if (i < n) g_deg[i] = 1.0f;   // self loop
}

__global__ void k_deg_count(const int* __restrict__ dst, int E) {
    int e = blockIdx.x * blockDim.x + threadIdx.x;
    if (e < E) atomicAdd(&g_deg[dst[e]], 1.0f);   // no return use -> RED
}

// ---------------------------------------------------------- layer 1 xform ----
__global__ void k_transform1(const float* __restrict__ x,
                             const float* __restrict__ W, int n) {
    __shared__ float sW[16][16];
    int t = threadIdx.x;
    if (t < 256) sW[t >> 4][t & 15] = W[t];
    __syncthreads();

    int i = blockIdx.x * blockDim.x + t;
    if (i >= n) return;

    float di = rsqrtf(g_deg[i]);
    g_dinv[i] = di;

    const float4* xr = (const float4*)(x + (size_t)i * FEAT);
    float4 xv[4];
#pragma unroll
    for (int q = 0; q < 4; q++) xv[q] = xr[q];
    float xin[16];
#pragma unroll
    for (int q = 0; q < 4; q++) {
        xin[4*q+0] = xv[q].x; xin[4*q+1] = xv[q].y;
        xin[4*q+2] = xv[q].z; xin[4*q+3] = xv[q].w;
    }

    float o[16];
#pragma unroll
    for (int j = 0; j < 16; j++) {
        float s = 0.0f;
#pragma unroll
        for (int k = 0; k < 16; k++) s = fmaf(xin[k], sW[k][j], s);
        o[j] = s * di;
    }

    float4* hp = &g_hs1[i * 4];
    float4* ap = &g_agg1[i * 4];
#pragma unroll
    for (int q = 0; q < 4; q++) {
        float4 v = make_float4(o[4*q], o[4*q+1], o[4*q+2], o[4*q+3]);
        hp[q] = v;
        ap[q] = v;    // self-loop contribution
    }
}

// ------------------------------------------------------------- scatter ------
template <int LAYER>
__global__ void k_scatter(const int* __restrict__ src,
                          const int* __restrict__ dst, int E) {
    int e = blockIdx.x * blockDim.x + threadIdx.x;
    if (e >= E) return;
    int s = src[e];
    int d = dst[e];
    const float4* hp = (LAYER == 1 ? g_hs1 : g_hs2) + (size_t)s * 4;
    float4 v0 = hp[0], v1 = hp[1], v2 = hp[2], v3 = hp[3];
    float4* ap = (LAYER == 1 ? g_agg1 : g_agg2) + (size_t)d * 4;
    red_add_v4(ap + 0, v0);
    red_add_v4(ap + 1, v1);
    red_add_v4(ap + 2, v2);
    red_add_v4(ap + 3, v3);
}

// ------------------------------------------- layer1 epilogue + layer2 xform -
__global__ void k_transform2(const float* __restrict__ W2,
                             const float* __restrict__ b1, int n) {
    __shared__ float sW[16][16];
    __shared__ float sb[16];
    int t = threadIdx.x;
    if (t < 256) sW[t >> 4][t & 15] = W2[t];
    if (t < 16) sb[t] = b1[t];
    __syncthreads();

    int i = blockIdx.x * blockDim.x + t;
    if (i >= n) return;

    float di = g_dinv[i];
    const float4* ap1 = &g_agg1[i * 4];
    float4 av[4];
#pragma unroll
    for (int q = 0; q < 4; q++) av[q] = ap1[q];

    float hin[16];
#pragma unroll
    for (int q = 0; q < 4; q++) {
        hin[4*q+0] = av[q].x; hin[4*q+1] = av[q].y;
        hin[4*q+2] = av[q].z; hin[4*q+3] = av[q].w;
    }
#pragma unroll
    for (int k = 0; k < 16; k++)
        hin[k] = fmaxf(fmaf(hin[k], di, sb[k]), 0.0f);   // *dinv + b1, relu

    float o[16];
#pragma unroll
    for (int j = 0; j < 16; j++) {
        float s = 0.0f;
#pragma unroll
        for (int k = 0; k < 16; k++) s = fmaf(hin[k], sW[k][j], s);
        o[j] = s * di;
    }

    float4* hp = &g_hs2[i * 4];
    float4* ap = &g_agg2[i * 4];
#pragma unroll
    for (int q = 0; q < 4; q++) {
        float4 v = make_float4(o[4*q], o[4*q+1], o[4*q+2], o[4*q+3]);
        hp[q] = v;
        ap[q] = v;    // self loop
    }
}

// ------------------------------------------------------------- epilogue -----
__global__ void k_epilogue(float* __restrict__ out,
                           const float* __restrict__ b2, int n) {
    __shared__ float sb[16];
    int t = threadIdx.x;
    if (t < 16) sb[t] = b2[t];
    __syncthreads();

    int i = blockIdx.x * blockDim.x + t;
    if (i >= n) return;

    float di = g_dinv[i];
    const float4* ap = &g_agg2[i * 4];
    float4* op = (float4*)(out + (size_t)i * FEAT);
#pragma unroll
    for (int q = 0; q < 4; q++) {
        float4 v = ap[q];
        v.x = fmaf(v.x, di, sb[4*q+0]);
        v.y = fmaf(v.y, di, sb[4*q+1]);
        v.z = fmaf(v.z, di, sb[4*q+2]);
        v.w = fmaf(v.w, di, sb[4*q+3]);
        op[q] = v;
    }
}

// ---------------------------------------------------------------- launch ----
extern "C" void kernel_launch(void* const* d_in, const int* in_sizes, int n_in,
                              void* d_out, int out_size) {
    const float* x    = (const float*)d_in[0];
    const int*   eidx = (const int*)  d_in[1];
    const float* W1   = (const float*)d_in[2];
    const float* b1   = (const float*)d_in[3];
    const float* W2   = (const float*)d_in[4];
    const float* b2   = (const float*)d_in[5];
    float* out = (float*)d_out;

    int n = in_sizes[0] / FEAT;       // 100000
    int E = in_sizes[1] / 2;          // 3200000
    const int* src = eidx;
    const int* dst = eidx + E;

    const int B = 256;
    int gn = (n + B - 1) / B;
    int ge = (E + B - 1) / B;

    k_deg_init  <<<gn, B>>>(n);
    k_deg_count <<<ge, B>>>(dst, E);
    k_transform1<<<gn, B>>>(x, W1, n);
    k_scatter<1><<<ge, B>>>(src, dst, E);
    k_transform2<<<gn, B>>>(W2, b1, n);
    k_scatter<2><<<ge, B>>>(src, dst, E);
    k_epilogue  <<<gn, B>>>(out, b2, n);
}

// round 3
// speedup vs baseline: 1.5455x; 1.5455x over previous
#include <cuda_runtime.h>

#define N_NODES 100000
#define FEAT 16

// Scratch in __device__ globals (no allocations allowed).
__device__ float  g_deg [N_NODES];
__device__ float  g_dinv[N_NODES];
__device__ float4 g_hs1 [N_NODES * 4];   // layer1 transformed+src-scaled features
__device__ float4 g_agg1[N_NODES * 4];   // layer1 aggregation (init = hs1 -> self loop)
__device__ float4 g_hs2 [N_NODES * 4];
__device__ float4 g_agg2[N_NODES * 4];

__device__ __forceinline__ void red_add_v4(float4* p, float4 v) {
    asm volatile("red.global.add.v4.f32 [%0], {%1, %2, %3, %4};"
                 :: "l"(p), "f"(v.x), "f"(v.y), "f"(v.z), "f"(v.w)
                 : "memory");
}

// ---------------------------------------------------------------- degree ----
__global__ void k_deg_init(int n) {
    int i = blockIdx.x * blockDim.x + threadIdx.x;
    if (i < n) g_deg[i] = 1.0f;   // self loop
}

__global__ void k_deg_count(const int* __restrict__ dst, int E) {
    int e = blockIdx.x * blockDim.x + threadIdx.x;
    if (e < E) atomicAdd(&g_deg[dst[e]], 1.0f);   // no return use -> RED
}

// ---------------------------------------------------------- layer 1 xform ----
__global__ void k_transform1(const float* __restrict__ x,
                             const float* __restrict__ W, int n) {
    __shared__ float sW[16][16];
    int t = threadIdx.x;
    if (t < 256) sW[t >> 4][t & 15] = W[t];
    __syncthreads();

    int i = blockIdx.x * blockDim.x + t;
    if (i >= n) return;

    float di = rsqrtf(g_deg[i]);
    g_dinv[i] = di;

    const float4* xr = (const float4*)(x + (size_t)i * FEAT);
    float4 xv[4];
#pragma unroll
    for (int q = 0; q < 4; q++) xv[q] = xr[q];
    float xin[16];
#pragma unroll
    for (int q = 0; q < 4; q++) {
        xin[4*q+0] = xv[q].x; xin[4*q+1] = xv[q].y;
        xin[4*q+2] = xv[q].z; xin[4*q+3] = xv[q].w;
    }

    float o[16];
#pragma unroll
    for (int j = 0; j < 16; j++) {
        float s = 0.0f;
#pragma unroll
        for (int k = 0; k < 16; k++) s = fmaf(xin[k], sW[k][j], s);
        o[j] = s * di;
    }

    float4* hp = &g_hs1[i * 4];
    float4* ap = &g_agg1[i * 4];
#pragma unroll
    for (int q = 0; q < 4; q++) {
        float4 v = make_float4(o[4*q], o[4*q+1], o[4*q+2], o[4*q+3]);
        hp[q] = v;
        ap[q] = v;    // self-loop contribution
    }
}

// ------------------------------------------------------------- scatter ------
// 4 threads cooperate on one edge: thread q handles float4 quarter q.
// Per warp: 8 edges; the 4 threads of an edge touch 64 consecutive bytes
// -> 1-2 L1 wavefronts per edge instead of ~32 per LDG.128.
template <int LAYER>
__global__ void k_scatter4(const int* __restrict__ src,
                           const int* __restrict__ dst, int E) {
    int t = blockIdx.x * blockDim.x + threadIdx.x;
    int e = t >> 2;
    int q = t & 3;
    if (e >= E) return;
    int s = __ldg(src + e);   // broadcast within 4-thread group
    int d = __ldg(dst + e);
    const float4* hs = (LAYER == 1 ? g_hs1 : g_hs2);
    float4*       ag = (LAYER == 1 ? g_agg1 : g_agg2);
    float4 v = __ldg(hs + (size_t)s * 4 + q);
    red_add_v4(ag + (size_t)d * 4 + q, v);
}

// ------------------------------------------- layer1 epilogue + layer2 xform -
__global__ void k_transform2(const float* __restrict__ W2,
                             const float* __restrict__ b1, int n) {
    __shared__ float sW[16][16];
    __shared__ float sb[16];
    int t = threadIdx.x;
    if (t < 256) sW[t >> 4][t & 15] = W2[t];
    if (t < 16) sb[t] = b1[t];
    __syncthreads();

    int i = blockIdx.x * blockDim.x + t;
    if (i >= n) return;

    float di = g_dinv[i];
    const float4* ap1 = &g_agg1[i * 4];
    float4 av[4];
#pragma unroll
    for (int q = 0; q < 4; q++) av[q] = ap1[q];

    float hin[16];
#pragma unroll
    for (int q = 0; q < 4; q++) {
        hin[4*q+0] = av[q].x; hin[4*q+1] = av[q].y;
        hin[4*q+2] = av[q].z; hin[4*q+3] = av[q].w;
    }
#pragma unroll
    for (int k = 0; k < 16; k++)
        hin[k] = fmaxf(fmaf(hin[k], di, sb[k]), 0.0f);   // *dinv + b1, relu

    float o[16];
#pragma unroll
    for (int j = 0; j < 16; j++) {
        float s = 0.0f;
#pragma unroll
        for (int k = 0; k < 16; k++) s = fmaf(hin[k], sW[k][j], s);
        o[j] = s * di;
    }

    float4* hp = &g_hs2[i * 4];
    float4* ap = &g_agg2[i * 4];
#pragma unroll
    for (int q = 0; q < 4; q++) {
        float4 v = make_float4(o[4*q], o[4*q+1], o[4*q+2], o[4*q+3]);
        hp[q] = v;
        ap[q] = v;    // self loop
    }
}

// ------------------------------------------------------------- epilogue -----
__global__ void k_epilogue(float* __restrict__ out,
                           const float* __restrict__ b2, int n) {
    __shared__ float sb[16];
    int t = threadIdx.x;
    if (t < 16) sb[t] = b2[t];
    __syncthreads();

    int i = blockIdx.x * blockDim.x + t;
    if (i >= n) return;

    float di = g_dinv[i];
    const float4* ap = &g_agg2[i * 4];
    float4* op = (float4*)(out + (size_t)i * FEAT);
#pragma unroll
    for (int q = 0; q < 4; q++) {
        float4 v = ap[q];
        v.x = fmaf(v.x, di, sb[4*q+0]);
        v.y = fmaf(v.y, di, sb[4*q+1]);
        v.z = fmaf(v.z, di, sb[4*q+2]);
        v.w = fmaf(v.w, di, sb[4*q+3]);
        op[q] = v;
    }
}

// ---------------------------------------------------------------- launch ----
extern "C" void kernel_launch(void* const* d_in, const int* in_sizes, int n_in,
                              void* d_out, int out_size) {
    const float* x    = (const float*)d_in[0];
    const int*   eidx = (const int*)  d_in[1];
    const float* W1   = (const float*)d_in[2];
    const float* b1   = (const float*)d_in[3];
    const float* W2   = (const float*)d_in[4];
    const float* b2   = (const float*)d_in[5];
    float* out = (float*)d_out;

    int n = in_sizes[0] / FEAT;       // 100000
    int E = in_sizes[1] / 2;          // 3200000
    const int* src = eidx;
    const int* dst = eidx + E;

    const int B = 256;
    int gn = (n + B - 1) / B;
    int ge = (E + B - 1) / B;
    long long tE = 4LL * E;           // 4 threads per edge
    int ge4 = (int)((tE + B - 1) / B);

    k_deg_init   <<<gn, B>>>(n);
    k_deg_count  <<<ge, B>>>(dst, E);
    k_transform1 <<<gn, B>>>(x, W1, n);
    k_scatter4<1><<<ge4, B>>>(src, dst, E);
    k_transform2 <<<gn, B>>>(W2, b1, n);
    k_scatter4<2><<<ge4, B>>>(src, dst, E);
    k_epilogue   <<<gn, B>>>(out, b2, n);
}